// round 1
// baseline (speedup 1.0000x reference)
#include <cuda_runtime.h>
#include <math.h>

#define NB   256
#define LCC  400
#define LQQ  50
#define DD   128
#define SROW 51      // padded S row stride (floats)
#define XPAD 132     // padded row stride for D-vectors
#define QP   52      // padded q stride for transposed Yq
#define CCHUNK 128
#define NT   512

// smem offsets (floats)
#define OFF_S    0                    // 400*51   = 20400
#define OFF_XQ   20400                // 52*132   = 6864
#define OFF_YQT  27264                // 128*52   = 6656
#define OFF_XC   33920                // 128*132  = 16896
#define OFF_TMP  (OFF_XC + 4096)     // 52*132 = 6864, aliased inside sXc (rows >= 31)
#define OFF_SB   OFF_XC              // 64*50 = 3200, aliased at sXc start
#define OFF_RMAX 50816               // 400
#define OFF_RINV 51216               // 400
#define OFF_CMAX 51616               // 52
#define OFF_CINV 51668               // 52
#define OFF_QW1  51720               // 52
#define SMEM_FLOATS 51772            // 207088 bytes

#define RES_ELEMS ((size_t)NB * LCC * 4 * DD)      // 52,428,800

__global__ __launch_bounds__(NT, 1)
void cqa_kernel(const float* __restrict__ xc_g, const float* __restrict__ xq_g,
                const float* __restrict__ W0, const float* __restrict__ W1,
                const float* __restrict__ W2, const int* __restrict__ clen_g,
                const int* __restrict__ qlen_g, float* __restrict__ out)
{
    extern __shared__ float sm[];
    const int b   = blockIdx.x;
    const int tid = threadIdx.x;
    const float* xcB = xc_g + (size_t)b * LCC * DD;
    const float* xqB = xq_g + (size_t)b * LQQ * DD;
    const int clen = clen_g[b];
    const int qlen = qlen_g[b];

    float* sS   = sm + OFF_S;
    float* sXq  = sm + OFF_XQ;
    float* sYqT = sm + OFF_YQT;
    float* sXc  = sm + OFF_XC;
    float* sTmp = sm + OFF_TMP;
    float* sSb  = sm + OFF_SB;
    float* sRMax = sm + OFF_RMAX;
    float* sRInv = sm + OFF_RINV;
    float* sCMax = sm + OFF_CMAX;
    float* sCInv = sm + OFF_CINV;
    float* sQW1  = sm + OFF_QW1;

    // ---------------- Phase 0: stage xq + build YqT = (xq*W2 + W0)^T ----------------
    for (int idx = tid; idx < LQQ * 32; idx += NT) {
        int q  = idx >> 5;
        int c4 = (idx & 31) * 4;
        float4 v  = *(const float4*)&xqB[q * DD + c4];
        *(float4*)&sXq[q * XPAD + c4] = v;
        float4 w2 = *(const float4*)&W2[c4];
        float4 w0 = *(const float4*)&W0[c4];
        sYqT[(c4 + 0) * QP + q] = fmaf(v.x, w2.x, w0.x);
        sYqT[(c4 + 1) * QP + q] = fmaf(v.y, w2.y, w0.y);
        sYqT[(c4 + 2) * QP + q] = fmaf(v.z, w2.z, w0.z);
        sYqT[(c4 + 3) * QP + q] = fmaf(v.w, w2.w, w0.w);
    }
    __syncthreads();
    // qW1[q] = xq[q] . W1
    if (tid < LQQ) {
        float s = 0.f;
        #pragma unroll 8
        for (int d = 0; d < DD; d += 4) {
            float4 xv = *(const float4*)&sXq[tid * XPAD + d];
            float4 wv = *(const float4*)&W1[d];
            s = fmaf(xv.x, wv.x, s); s = fmaf(xv.y, wv.y, s);
            s = fmaf(xv.z, wv.z, s); s = fmaf(xv.w, wv.w, s);
        }
        sQW1[tid] = s;
    }

    // ---------------- Phase 1: S[c,q] = qW1[q] + xc[c,:] . YqT[:,q] ----------------
    for (int cb = 0; cb < LCC; cb += CCHUNK) {
        const int cn = min(CCHUNK, LCC - cb);
        __syncthreads();
        for (int idx = tid; idx < cn * 32; idx += NT) {
            int r  = idx >> 5;
            int c4 = (idx & 31) * 4;
            *(float4*)&sXc[r * XPAD + c4] = *(const float4*)&xcB[(size_t)(cb + r) * DD + c4];
        }
        __syncthreads();
        if (tid < 416) {
            const int qg = tid % 13, cg = tid / 13;
            const int q0 = qg * 4, c0 = cg * 4;
            if (c0 < cn) {
                const int ci0 = c0;
                const int ci1 = min(c0 + 1, cn - 1);
                const int ci2 = min(c0 + 2, cn - 1);
                const int ci3 = min(c0 + 3, cn - 1);
                const float qw0 = sQW1[min(q0 + 0, LQQ - 1)];
                const float qw1 = sQW1[min(q0 + 1, LQQ - 1)];
                const float qw2 = sQW1[min(q0 + 2, LQQ - 1)];
                const float qw3 = sQW1[min(q0 + 3, LQQ - 1)];
                float4 a0 = make_float4(qw0, qw1, qw2, qw3);
                float4 a1 = a0, a2 = a0, a3 = a0;
                #pragma unroll 4
                for (int d4 = 0; d4 < DD; d4 += 4) {
                    float4 x0 = *(const float4*)&sXc[ci0 * XPAD + d4];
                    float4 x1 = *(const float4*)&sXc[ci1 * XPAD + d4];
                    float4 x2 = *(const float4*)&sXc[ci2 * XPAD + d4];
                    float4 x3 = *(const float4*)&sXc[ci3 * XPAD + d4];
                    const float* xa0 = (const float*)&x0;
                    const float* xa1 = (const float*)&x1;
                    const float* xa2 = (const float*)&x2;
                    const float* xa3 = (const float*)&x3;
                    #pragma unroll
                    for (int dd = 0; dd < 4; ++dd) {
                        float4 yv = *(const float4*)&sYqT[(d4 + dd) * QP + q0];
                        float v0 = xa0[dd], v1 = xa1[dd], v2 = xa2[dd], v3 = xa3[dd];
                        a0.x = fmaf(v0, yv.x, a0.x); a0.y = fmaf(v0, yv.y, a0.y);
                        a0.z = fmaf(v0, yv.z, a0.z); a0.w = fmaf(v0, yv.w, a0.w);
                        a1.x = fmaf(v1, yv.x, a1.x); a1.y = fmaf(v1, yv.y, a1.y);
                        a1.z = fmaf(v1, yv.z, a1.z); a1.w = fmaf(v1, yv.w, a1.w);
                        a2.x = fmaf(v2, yv.x, a2.x); a2.y = fmaf(v2, yv.y, a2.y);
                        a2.z = fmaf(v2, yv.z, a2.z); a2.w = fmaf(v2, yv.w, a2.w);
                        a3.x = fmaf(v3, yv.x, a3.x); a3.y = fmaf(v3, yv.y, a3.y);
                        a3.z = fmaf(v3, yv.z, a3.z); a3.w = fmaf(v3, yv.w, a3.w);
                    }
                }
                const int cgl = cb + c0;
                #define STORE_S(i, A)                                                 \
                    if (c0 + (i) < cn) {                                              \
                        float* row = &sS[(cgl + (i)) * SROW + q0];                    \
                        row[0] = A.x;                                                 \
                        if (q0 + 1 < LQQ) row[1] = A.y;                               \
                        if (q0 + 2 < LQQ) row[2] = A.z;                               \
                        if (q0 + 3 < LQQ) row[3] = A.w;                               \
                    }
                STORE_S(0, a0) STORE_S(1, a1) STORE_S(2, a2) STORE_S(3, a3)
                #undef STORE_S
            }
        }
    }
    __syncthreads();

    // ---------------- Phase 2: row stats + S_bar -> gmem ----------------
    if (tid < LCC) {
        const float* row = &sS[tid * SROW];
        float m = -3.0e38f;
        for (int q = 0; q < LQQ; ++q) {
            float v = row[q] - (q < qlen ? 0.f : 1e12f);
            m = fmaxf(m, v);
        }
        float sum = 0.f;
        for (int q = 0; q < LQQ; ++q) {
            float v = row[q] - (q < qlen ? 0.f : 1e12f);
            sum += __expf(v - m);
        }
        sRMax[tid] = m;
        sRInv[tid] = 1.f / sum;
    }
    __syncthreads();
    float* sbar_g = out + RES_ELEMS + (size_t)b * LCC * LQQ;
    for (int idx = tid; idx < LCC * LQQ; idx += NT) {
        int c = idx / LQQ, q = idx - c * LQQ;
        float v = sS[c * SROW + q] - (q < qlen ? 0.f : 1e12f);
        sbar_g[idx] = __expf(v - sRMax[c]) * sRInv[c];
    }

    // ---------------- Phase 3: column stats, transform S->P in place, S_T -> gmem ----------------
    {
        const int g = tid >> 3, s8 = tid & 7;
        float m = -3.0e38f;
        if (g < LQQ) {
            for (int c = s8; c < LCC; c += 8) {
                float v = sS[c * SROW + g] - (c < clen ? 0.f : 1e12f);
                m = fmaxf(m, v);
            }
        }
        m = fmaxf(m, __shfl_xor_sync(0xffffffffu, m, 1));
        m = fmaxf(m, __shfl_xor_sync(0xffffffffu, m, 2));
        m = fmaxf(m, __shfl_xor_sync(0xffffffffu, m, 4));
        float sum = 0.f;
        if (g < LQQ) {
            for (int c = s8; c < LCC; c += 8) {
                float v = sS[c * SROW + g] - (c < clen ? 0.f : 1e12f);
                sum += __expf(v - m);
            }
        }
        sum += __shfl_xor_sync(0xffffffffu, sum, 1);
        sum += __shfl_xor_sync(0xffffffffu, sum, 2);
        sum += __shfl_xor_sync(0xffffffffu, sum, 4);
        if (g < LQQ && s8 == 0) { sCMax[g] = m; sCInv[g] = 1.f / sum; }
    }
    __syncthreads();
    for (int idx = tid; idx < LCC * LQQ; idx += NT) {
        int c = idx / LQQ, q = idx - c * LQQ;
        float v = sS[c * SROW + q] - (c < clen ? 0.f : 1e12f);
        sS[c * SROW + q] = __expf(v - sCMax[q]) * sCInv[q];
    }
    __syncthreads();
    float* st_g = out + RES_ELEMS + (size_t)NB * LCC * LQQ + (size_t)b * LQQ * LCC;
    for (int idx = tid; idx < LQQ * LCC; idx += NT) {
        int q = idx / LCC, c = idx - q * LCC;
        st_g[idx] = sS[c * SROW + q];
    }

    // ---------------- Phase 4: tmp[q,d] = sum_c P[c,q] * xc[c,d] ----------------
    const int dg = tid & 31;
    {
        const int qg = tid >> 5;
        const int q0 = qg * 4;
        const int qi0 = min(q0 + 0, LQQ - 1), qi1 = min(q0 + 1, LQQ - 1);
        const int qi2 = min(q0 + 2, LQQ - 1), qi3 = min(q0 + 3, LQQ - 1);
        float4 t0 = make_float4(0,0,0,0), t1 = t0, t2 = t0, t3 = t0;
        for (int cb = 0; cb < LCC; cb += CCHUNK) {
            const int cn = min(CCHUNK, LCC - cb);
            __syncthreads();
            for (int idx = tid; idx < cn * 32; idx += NT) {
                int r  = idx >> 5;
                int c4 = (idx & 31) * 4;
                *(float4*)&sXc[r * XPAD + c4] = *(const float4*)&xcB[(size_t)(cb + r) * DD + c4];
            }
            __syncthreads();
            if (q0 < LQQ) {
                #pragma unroll 2
                for (int c = 0; c < cn; ++c) {
                    float4 xv = *(const float4*)&sXc[c * XPAD + dg * 4];
                    const float* prow = &sS[(cb + c) * SROW];
                    float p0 = prow[qi0], p1 = prow[qi1], p2 = prow[qi2], p3 = prow[qi3];
                    t0.x = fmaf(p0, xv.x, t0.x); t0.y = fmaf(p0, xv.y, t0.y);
                    t0.z = fmaf(p0, xv.z, t0.z); t0.w = fmaf(p0, xv.w, t0.w);
                    t1.x = fmaf(p1, xv.x, t1.x); t1.y = fmaf(p1, xv.y, t1.y);
                    t1.z = fmaf(p1, xv.z, t1.z); t1.w = fmaf(p1, xv.w, t1.w);
                    t2.x = fmaf(p2, xv.x, t2.x); t2.y = fmaf(p2, xv.y, t2.y);
                    t2.z = fmaf(p2, xv.z, t2.z); t2.w = fmaf(p2, xv.w, t2.w);
                    t3.x = fmaf(p3, xv.x, t3.x); t3.y = fmaf(p3, xv.y, t3.y);
                    t3.z = fmaf(p3, xv.z, t3.z); t3.w = fmaf(p3, xv.w, t3.w);
                }
            }
        }
        __syncthreads();
        if (q0 + 0 < LQQ) *(float4*)&sTmp[(q0 + 0) * XPAD + dg * 4] = t0;
        if (q0 + 1 < LQQ) *(float4*)&sTmp[(q0 + 1) * XPAD + dg * 4] = t1;
        if (q0 + 2 < LQQ) *(float4*)&sTmp[(q0 + 2) * XPAD + dg * 4] = t2;
        if (q0 + 3 < LQQ) *(float4*)&sTmp[(q0 + 3) * XPAD + dg * 4] = t3;
    }

    // ---------------- Phase 5: c2q = Sb@xq, q2c = Sb@tmp, fused epilogue ----------------
    {
        const int cg = tid >> 5;
        for (int cb = 0; cb < LCC; cb += 64) {
            const int cn = min(64, LCC - cb);
            __syncthreads();
            for (int idx = tid; idx < cn * LQQ; idx += NT)
                sSb[idx] = sbar_g[(size_t)cb * LQQ + idx];
            __syncthreads();
            const int c0 = cg * 4;
            if (c0 < cn) {
                const int li0 = c0;
                const int li1 = min(c0 + 1, cn - 1);
                const int li2 = min(c0 + 2, cn - 1);
                const int li3 = min(c0 + 3, cn - 1);
                float4 a10 = make_float4(0,0,0,0), a11 = a10, a12 = a10, a13 = a10;
                float4 a20 = a10, a21 = a10, a22 = a10, a23 = a10;
                #pragma unroll 2
                for (int q = 0; q < LQQ; ++q) {
                    float4 xqv = *(const float4*)&sXq[q * XPAD + dg * 4];
                    float4 tv  = *(const float4*)&sTmp[q * XPAD + dg * 4];
                    float s0 = sSb[li0 * LQQ + q];
                    float s1 = sSb[li1 * LQQ + q];
                    float s2 = sSb[li2 * LQQ + q];
                    float s3 = sSb[li3 * LQQ + q];
                    a10.x = fmaf(s0, xqv.x, a10.x); a10.y = fmaf(s0, xqv.y, a10.y);
                    a10.z = fmaf(s0, xqv.z, a10.z); a10.w = fmaf(s0, xqv.w, a10.w);
                    a11.x = fmaf(s1, xqv.x, a11.x); a11.y = fmaf(s1, xqv.y, a11.y);
                    a11.z = fmaf(s1, xqv.z, a11.z); a11.w = fmaf(s1, xqv.w, a11.w);
                    a12.x = fmaf(s2, xqv.x, a12.x); a12.y = fmaf(s2, xqv.y, a12.y);
                    a12.z = fmaf(s2, xqv.z, a12.z); a12.w = fmaf(s2, xqv.w, a12.w);
                    a13.x = fmaf(s3, xqv.x, a13.x); a13.y = fmaf(s3, xqv.y, a13.y);
                    a13.z = fmaf(s3, xqv.z, a13.z); a13.w = fmaf(s3, xqv.w, a13.w);
                    a20.x = fmaf(s0, tv.x, a20.x); a20.y = fmaf(s0, tv.y, a20.y);
                    a20.z = fmaf(s0, tv.z, a20.z); a20.w = fmaf(s0, tv.w, a20.w);
                    a21.x = fmaf(s1, tv.x, a21.x); a21.y = fmaf(s1, tv.y, a21.y);
                    a21.z = fmaf(s1, tv.z, a21.z); a21.w = fmaf(s1, tv.w, a21.w);
                    a22.x = fmaf(s2, tv.x, a22.x); a22.y = fmaf(s2, tv.y, a22.y);
                    a22.z = fmaf(s2, tv.z, a22.z); a22.w = fmaf(s2, tv.w, a22.w);
                    a23.x = fmaf(s3, tv.x, a23.x); a23.y = fmaf(s3, tv.y, a23.y);
                    a23.z = fmaf(s3, tv.z, a23.z); a23.w = fmaf(s3, tv.w, a23.w);
                }
                #define EPI(i, A1, A2)                                                     \
                    if (c0 + (i) < cn) {                                                   \
                        int c = cb + c0 + (i);                                             \
                        float4 xcv = *(const float4*)&xcB[(size_t)c * DD + dg * 4];        \
                        float* orow = out + ((size_t)(b * LCC + c)) * (4 * DD);            \
                        *(float4*)&orow[dg * 4] = xcv;                                     \
                        *(float4*)&orow[DD + dg * 4] = A1;                                 \
                        float4 m1 = make_float4(xcv.x * A1.x, xcv.y * A1.y,                \
                                                xcv.z * A1.z, xcv.w * A1.w);               \
                        *(float4*)&orow[2 * DD + dg * 4] = m1;                             \
                        float4 m2 = make_float4(xcv.x * A2.x, xcv.y * A2.y,                \
                                                xcv.z * A2.z, xcv.w * A2.w);               \
                        *(float4*)&orow[3 * DD + dg * 4] = m2;                             \
                    }
                EPI(0, a10, a20) EPI(1, a11, a21) EPI(2, a12, a22) EPI(3, a13, a23)
                #undef EPI
            }
        }
    }
}

extern "C" void kernel_launch(void* const* d_in, const int* in_sizes, int n_in,
                              void* d_out, int out_size)
{
    const float* xc  = (const float*)d_in[0];
    const float* xq  = (const float*)d_in[1];
    const float* W0  = (const float*)d_in[2];
    const float* W1  = (const float*)d_in[3];
    const float* W2  = (const float*)d_in[4];
    const int* clen  = (const int*)d_in[5];
    const int* qlen  = (const int*)d_in[6];
    float* out = (float*)d_out;

    const int smem_bytes = SMEM_FLOATS * (int)sizeof(float);
    cudaFuncSetAttribute(cqa_kernel, cudaFuncAttributeMaxDynamicSharedMemorySize, smem_bytes);
    cqa_kernel<<<NB, NT, smem_bytes>>>(xc, xq, W0, W1, W2, clen, qlen, out);
}